// round 16
// baseline (speedup 1.0000x reference)
#include <cuda_runtime.h>
#include <cuda_fp16.h>
#include <stdint.h>
#include <math.h>

#define D 128
#define MAXN 100000
#define MAXE 1600000
#define MAXG 512

#define SZH 68            // half2 stride of A rows in smem
#define SWH 132           // half2 stride of B k2-rows in smem (and gmem image)
#define WIMG (64 * SWH)   // half2 words per weight-matrix image
#define MLP_SMEM ((128 * SZH + 64 * SWH + 256 + 256) * 4)

// ---------------- scratch ----------------
__device__ __half g_h16A[MAXN * D];
__device__ __half g_h16B[MAXN * D];
__device__ __half g_x16[MAXN * D];
__device__ __half g_z16[MAXN * D];
__device__ unsigned g_wt[3 * 2 * WIMG];   // fp16 weight images, smem-ready layout
__device__ int   g_rowptr[MAXN + 1];
__device__ int   g_cursor[MAXN + 1];      // zeroed at load; self-cleaned by final_kernel
__device__ int   g_partial[256];
__device__ int   g_csrsrc[MAXE];
__device__ float g_stats[4 * D];          // two 256-float buffers; zeroed by prep each launch
__device__ float g_psum[MAXG * D];        // self-cleaned by final_kernel
__device__ int   g_pmax[MAXG * D];
__device__ int   g_pcnt[MAXG];

// ================= merged hist + prep =================
__global__ void histprep_kernel(const int* __restrict__ dst, int* __restrict__ deg, int nE,
                                const float* __restrict__ x, __half* __restrict__ x16,
                                const int* __restrict__ batch, int* __restrict__ pcnt,
                                const float* __restrict__ W1, const float* __restrict__ W2,
                                float* __restrict__ stats, int n,
                                int HB, int BX, int BC)
{
    int b = blockIdx.x;
    int tid = threadIdx.x;
    if (b < HB) {
        int e = b * 256 + tid;
        if (e < nE) atomicAdd(&deg[dst[e]], 1);
    } else if (b < HB + BX) {
        int i = (b - HB) * 256 + tid;
        if (i < n * 64) {
            float2 f = reinterpret_cast<const float2*>(x)[i];
            reinterpret_cast<__half2*>(x16)[i] = __floats2half2_rn(f.x, f.y);
        }
    } else if (b < HB + BX + BC) {
        int i = (b - HB - BX) * 256 + tid;
        if (i < n) atomicAdd(&pcnt[batch[i]], 1);
    } else if (b < HB + BX + BC + 192) {
        int i = (b - HB - BX - BC) * 256 + tid;
        if (i < 3 * 2 * 64 * 128) {
            int nn = i & 127;
            int k2 = (i >> 7) & 63;
            int m  = (i >> 13) & 1;
            int l  = i >> 14;
            const float* W = (m == 0 ? W1 : W2) + l * D * D;
            __half2 v = __floats2half2_rn(W[(2 * k2) * D + nn], W[(2 * k2 + 1) * D + nn]);
            int perm = (nn & 7) * 16 + (nn >> 3);
            g_wt[((l * 2 + m) * 64 + k2) * SWH + perm] = *reinterpret_cast<unsigned*>(&v);
        }
    } else {
        stats[tid] = 0.f;
        stats[256 + tid] = 0.f;
    }
}

#define SCAN_B 1024
__global__ void scan1_kernel(const int* __restrict__ deg, int* __restrict__ rowptr,
                             int* __restrict__ partial, int n)
{
    __shared__ int sh[SCAN_B];
    int i = blockIdx.x * SCAN_B + threadIdx.x;
    int v = (i < n) ? deg[i] : 0;
    sh[threadIdx.x] = v;
    __syncthreads();
    for (int o = 1; o < SCAN_B; o <<= 1) {
        int t = (threadIdx.x >= o) ? sh[threadIdx.x - o] : 0;
        __syncthreads();
        sh[threadIdx.x] += t;
        __syncthreads();
    }
    if (i < n) rowptr[i] = sh[threadIdx.x] - v;
    if (threadIdx.x == SCAN_B - 1) partial[blockIdx.x] = sh[SCAN_B - 1];
}

// adds block offsets (computed in-block from partials) AND initializes cursor = rowptr
__global__ void scan3_kernel(int* __restrict__ rowptr, int* __restrict__ cursor,
                             const int* __restrict__ partial, int n, int nb)
{
    __shared__ int sp[128];
    if (threadIdx.x < nb) sp[threadIdx.x] = partial[threadIdx.x];
    __syncthreads();
    int off = 0;
    for (int k = 0; k < blockIdx.x; k++) off += sp[k];
    int i = blockIdx.x * SCAN_B + threadIdx.x;
    if (i < n) {
        int v = rowptr[i] + off;
        rowptr[i] = v;
        cursor[i] = v;
    }
    if (i == 0) {
        int total = 0;
        for (int k = 0; k < nb; k++) total += sp[k];
        rowptr[n] = total;
    }
}

// 4 grid-strided edges per thread: 4 independent ATOMG in flight
__global__ void fill_kernel(const int* __restrict__ src, const int* __restrict__ dst,
                            int* __restrict__ cursor, int* __restrict__ csrsrc, int nE)
{
    int t = blockIdx.x * blockDim.x + threadIdx.x;
    int stride = gridDim.x * blockDim.x;
    int e0 = t, e1 = t + stride, e2 = t + 2 * stride, e3 = t + 3 * stride;
    bool v0 = e0 < nE, v1 = e1 < nE, v2 = e2 < nE, v3 = e3 < nE;
    int d0 = v0 ? dst[e0] : 0, d1 = v1 ? dst[e1] : 0;
    int d2 = v2 ? dst[e2] : 0, d3 = v3 ? dst[e3] : 0;
    int s0 = v0 ? src[e0] : 0, s1 = v1 ? src[e1] : 0;
    int s2 = v2 ? src[e2] : 0, s3 = v3 ? src[e3] : 0;
    int p0 = 0, p1 = 0, p2 = 0, p3 = 0;
    if (v0) p0 = atomicAdd(&cursor[d0], 1);
    if (v1) p1 = atomicAdd(&cursor[d1], 1);
    if (v2) p2 = atomicAdd(&cursor[d2], 1);
    if (v3) p3 = atomicAdd(&cursor[d3], 1);
    if (v0) csrsrc[p0] = s0;
    if (v1) csrsrc[p1] = s1;
    if (v2) csrsrc[p2] = s2;
    if (v3) csrsrc[p3] = s3;
}

// ================= gather: warp/node, half-warp per edge, inline BN fold ==========
__global__ __launch_bounds__(256) void gather16_kernel(
    const __half* __restrict__ h,
    const int* __restrict__ rowptr,
    const int* __restrict__ csrsrc,
    __half* __restrict__ z, int n, int apply_bn,
    const float* __restrict__ stats,
    const float* __restrict__ gamma, const float* __restrict__ beta, float inv_n)
{
    __shared__ float s_scale[128], s_shift[128];
    if (apply_bn) {
        if (threadIdx.x < 128) {
            int j = threadIdx.x;
            float mu = stats[j] * inv_n;
            float var = stats[D + j] * inv_n - mu * mu;
            float sc = gamma[j] * rsqrtf(var + 1e-5f);
            s_scale[j] = sc;
            s_shift[j] = beta[j] - mu * sc;
        }
        __syncthreads();
    }
    int node = (blockIdx.x * blockDim.x + threadIdx.x) >> 5;
    int lane = threadIdx.x & 31;
    int hf   = lane >> 4;
    int sl   = lane & 15;
    if (node >= n) return;
    int beg = rowptr[node], end = rowptr[node + 1];

    const uint4* h4 = reinterpret_cast<const uint4*>(h);

    float f[8];
    {
        uint4 sv = h4[(size_t)node * 16 + sl];
        const __half2* p = reinterpret_cast<const __half2*>(&sv);
        if (hf == 0) {
#pragma unroll
            for (int k = 0; k < 4; k++) {
                float2 t = __half22float2(p[k]);
                f[2 * k] = t.x; f[2 * k + 1] = t.y;
            }
        } else {
#pragma unroll
            for (int k = 0; k < 8; k++) f[k] = 0.f;
        }
    }

    const __half2 h2z = __float2half2_rn(0.f);

    for (int e0 = beg; e0 < end; e0 += 32) {
        int cnt = end - e0; if (cnt > 32) cnt = 32;
        int li = lane < cnt ? lane : cnt - 1;
        int s = csrsrc[e0 + li];

        __half2 ha[4], hb[4];
#pragma unroll
        for (int k = 0; k < 4; k++) { ha[k] = h2z; hb[k] = h2z; }

        int j = 0;
        for (; j + 4 <= cnt; j += 4) {
            int sjA = __shfl_sync(0xffffffffu, s, j + hf);
            int sjB = __shfl_sync(0xffffffffu, s, j + 2 + hf);
            uint4 va = h4[(size_t)sjA * 16 + sl];
            uint4 vb = h4[(size_t)sjB * 16 + sl];
            const __half2* pa = reinterpret_cast<const __half2*>(&va);
            const __half2* pb = reinterpret_cast<const __half2*>(&vb);
#pragma unroll
            for (int k = 0; k < 4; k++) {
                ha[k] = __hadd2(ha[k], pa[k]);
                hb[k] = __hadd2(hb[k], pb[k]);
            }
        }
        for (; j < cnt; j += 2) {
            int idx = j + hf;
            bool ok = idx < cnt;
            int sj = __shfl_sync(0xffffffffu, s, ok ? idx : 0);
            if (ok) {
                uint4 va = h4[(size_t)sj * 16 + sl];
                const __half2* pa = reinterpret_cast<const __half2*>(&va);
#pragma unroll
                for (int k = 0; k < 4; k++) ha[k] = __hadd2(ha[k], pa[k]);
            }
        }
        // flush chunk (each half2 acc held <= 8 fp16 adds)
#pragma unroll
        for (int k = 0; k < 4; k++) {
            float2 t0 = __half22float2(ha[k]);
            float2 t1 = __half22float2(hb[k]);
            f[2 * k]     += t0.x + t1.x;
            f[2 * k + 1] += t0.y + t1.y;
        }
    }

#pragma unroll
    for (int k = 0; k < 8; k++) f[k] += __shfl_xor_sync(0xffffffffu, f[k], 16);

    if (hf == 0) {
        if (apply_bn) {
            float m = 1.f + (float)(end - beg);
            int jb = sl * 8;
#pragma unroll
            for (int k = 0; k < 8; k++)
                f[k] = fmaf(f[k], s_scale[jb + k], m * s_shift[jb + k]);
        }
        uint4 out;
        __half2* o = reinterpret_cast<__half2*>(&out);
#pragma unroll
        for (int k = 0; k < 4; k++) o[k] = __floats2half2_rn(f[2 * k], f[2 * k + 1]);
        reinterpret_cast<uint4*>(z)[(size_t)node * 16 + sl] = out;
    }
}

// ================= fp16 tensor-core fused MLP (m16n8k16) =================
__device__ __forceinline__ void mma_f16(float* c, unsigned a0, unsigned a1,
                                        unsigned a2, unsigned a3,
                                        unsigned b0, unsigned b1)
{
    asm volatile("mma.sync.aligned.m16n8k16.row.col.f32.f16.f16.f32 "
                 "{%0,%1,%2,%3}, {%4,%5,%6,%7}, {%8,%9}, {%0,%1,%2,%3};"
                 : "+f"(c[0]), "+f"(c[1]), "+f"(c[2]), "+f"(c[3])
                 : "r"(a0), "r"(a1), "r"(a2), "r"(a3), "r"(b0), "r"(b1));
}

// mode 0: write h16 out + fused BN stats.  mode 2: fused mean/max pooling.
__global__ __launch_bounds__(256, 1) void mlp16_kernel(
    const __half* __restrict__ z,
    const unsigned* __restrict__ wimg1, const unsigned* __restrict__ wimg2,
    const float* __restrict__ b1, const float* __restrict__ b2,
    __half* __restrict__ hout, float* __restrict__ stats,
    const int* __restrict__ batch, float* __restrict__ psum, int* __restrict__ pmax,
    int n, int mode)
{
    extern __shared__ unsigned smu[];
    unsigned* s_z = smu;                               // [128][SZH] half2
    unsigned* s_w = smu + 128 * SZH;                   // [64][SWH] half2
    float* s_b1 = reinterpret_cast<float*>(smu + 128 * SZH + 64 * SWH);
    float* s_b2 = s_b1 + 128;
    float* s_st = s_b2 + 128;                          // [256] sum/sumsq (mode0) or sum/max (mode2)
    int*   s_sti = reinterpret_cast<int*>(s_st);
    __shared__ int s_bu;

    int tid  = threadIdx.x;
    int w    = tid >> 5;
    int lane = tid & 31;
    int g    = lane >> 2;
    int q    = lane & 3;
    int base = blockIdx.x * 128;
    int cnt  = n - base; if (cnt > 128) cnt = 128;

    if (tid < 128)      s_b1[tid] = b1[tid];
    else                s_b2[tid - 128] = b2[tid - 128];
    if (tid < 256)      s_st[tid] = 0.f;
    if (tid == 0)
        s_bu = (mode == 2 && cnt == 128 && batch[base] == batch[base + 127]) ? batch[base] : -1;

    // load Z tile (fp16, strided rows)
    const uint4* z4 = reinterpret_cast<const uint4*>(z);
#pragma unroll
    for (int it = 0; it < 8; it++) {
        int i = it * 256 + tid;
        int r = i >> 4, c8 = i & 15;
        uint4 v = (r < cnt) ? z4[(size_t)(base + r) * 16 + c8] : make_uint4(0u, 0u, 0u, 0u);
        *reinterpret_cast<uint4*>(s_z + r * SZH + c8 * 4) = v;
    }
    // load W1 image
    const uint4* w14 = reinterpret_cast<const uint4*>(wimg1);
#pragma unroll
    for (int it = 0; it < 9; it++) {
        int i = it * 256 + tid;
        if (i < WIMG / 4) reinterpret_cast<uint4*>(s_w)[i] = w14[i];
    }
    __syncthreads();

    int row0 = w * 16 + g;

    // ---- GEMM1: T = relu(Z @ W1 + b1) ----
    float acc[16][4];
#pragma unroll
    for (int nt = 0; nt < 16; nt++) {
        float bv0 = s_b1[nt * 8 + 2 * q], bv1 = s_b1[nt * 8 + 2 * q + 1];
        acc[nt][0] = bv0; acc[nt][1] = bv1; acc[nt][2] = bv0; acc[nt][3] = bv1;
    }
#pragma unroll
    for (int k8 = 0; k8 < 8; k8++) {
        int kq = k8 * 8 + q;
        unsigned a0 = s_z[row0 * SZH + kq];
        unsigned a1 = s_z[(row0 + 8) * SZH + kq];
        unsigned a2 = s_z[row0 * SZH + kq + 4];
        unsigned a3 = s_z[(row0 + 8) * SZH + kq + 4];
        unsigned B0[16], B1[16];
        const unsigned* r0p = s_w + kq * SWH + g * 16;
        const unsigned* r1p = s_w + (kq + 4) * SWH + g * 16;
        *reinterpret_cast<uint4*>(&B0[0])  = *reinterpret_cast<const uint4*>(r0p + 0);
        *reinterpret_cast<uint4*>(&B0[4])  = *reinterpret_cast<const uint4*>(r0p + 4);
        *reinterpret_cast<uint4*>(&B0[8])  = *reinterpret_cast<const uint4*>(r0p + 8);
        *reinterpret_cast<uint4*>(&B0[12]) = *reinterpret_cast<const uint4*>(r0p + 12);
        *reinterpret_cast<uint4*>(&B1[0])  = *reinterpret_cast<const uint4*>(r1p + 0);
        *reinterpret_cast<uint4*>(&B1[4])  = *reinterpret_cast<const uint4*>(r1p + 4);
        *reinterpret_cast<uint4*>(&B1[8])  = *reinterpret_cast<const uint4*>(r1p + 8);
        *reinterpret_cast<uint4*>(&B1[12]) = *reinterpret_cast<const uint4*>(r1p + 12);
#pragma unroll
        for (int nt = 0; nt < 16; nt++)
            mma_f16(acc[nt], a0, a1, a2, a3, B0[nt], B1[nt]);
    }
    __syncthreads();

    // store relu(T) as fp16 into freed s_z; load W2 image
#pragma unroll
    for (int nt = 0; nt < 16; nt++) {
        int hI = nt * 4 + q;
        __half2 v0 = __floats2half2_rn(fmaxf(acc[nt][0], 0.f), fmaxf(acc[nt][1], 0.f));
        __half2 v1 = __floats2half2_rn(fmaxf(acc[nt][2], 0.f), fmaxf(acc[nt][3], 0.f));
        s_z[row0 * SZH + hI]       = *reinterpret_cast<unsigned*>(&v0);
        s_z[(row0 + 8) * SZH + hI] = *reinterpret_cast<unsigned*>(&v1);
    }
    const uint4* w24 = reinterpret_cast<const uint4*>(wimg2);
#pragma unroll
    for (int it = 0; it < 9; it++) {
        int i = it * 256 + tid;
        if (i < WIMG / 4) reinterpret_cast<uint4*>(s_w)[i] = w24[i];
    }
    __syncthreads();

    // ---- GEMM2: H = relu(T @ W2 + b2) ----
#pragma unroll
    for (int nt = 0; nt < 16; nt++) {
        float bv0 = s_b2[nt * 8 + 2 * q], bv1 = s_b2[nt * 8 + 2 * q + 1];
        acc[nt][0] = bv0; acc[nt][1] = bv1; acc[nt][2] = bv0; acc[nt][3] = bv1;
    }
#pragma unroll
    for (int k8 = 0; k8 < 8; k8++) {
        int kq = k8 * 8 + q;
        unsigned a0 = s_z[row0 * SZH + kq];
        unsigned a1 = s_z[(row0 + 8) * SZH + kq];
        unsigned a2 = s_z[row0 * SZH + kq + 4];
        unsigned a3 = s_z[(row0 + 8) * SZH + kq + 4];
        unsigned B0[16], B1[16];
        const unsigned* r0p = s_w + kq * SWH + g * 16;
        const unsigned* r1p = s_w + (kq + 4) * SWH + g * 16;
        *reinterpret_cast<uint4*>(&B0[0])  = *reinterpret_cast<const uint4*>(r0p + 0);
        *reinterpret_cast<uint4*>(&B0[4])  = *reinterpret_cast<const uint4*>(r0p + 4);
        *reinterpret_cast<uint4*>(&B0[8])  = *reinterpret_cast<const uint4*>(r0p + 8);
        *reinterpret_cast<uint4*>(&B0[12]) = *reinterpret_cast<const uint4*>(r0p + 12);
        *reinterpret_cast<uint4*>(&B1[0])  = *reinterpret_cast<const uint4*>(r1p + 0);
        *reinterpret_cast<uint4*>(&B1[4])  = *reinterpret_cast<const uint4*>(r1p + 4);
        *reinterpret_cast<uint4*>(&B1[8])  = *reinterpret_cast<const uint4*>(r1p + 8);
        *reinterpret_cast<uint4*>(&B1[12]) = *reinterpret_cast<const uint4*>(r1p + 12);
#pragma unroll
        for (int nt = 0; nt < 16; nt++)
            mma_f16(acc[nt], a0, a1, a2, a3, B0[nt], B1[nt]);
    }

    bool ok0 = (row0 < cnt), ok1 = (row0 + 8 < cnt);

    if (mode != 2) {
        __half2* o0 = reinterpret_cast<__half2*>(hout + (size_t)(base + row0) * 128);
        __half2* o1 = reinterpret_cast<__half2*>(hout + (size_t)(base + row0 + 8) * 128);
#pragma unroll
        for (int nt = 0; nt < 16; nt++) {
            int c0 = nt * 8 + 2 * q;
            float v00 = fmaxf(acc[nt][0], 0.f), v01 = fmaxf(acc[nt][1], 0.f);
            float v10 = fmaxf(acc[nt][2], 0.f), v11 = fmaxf(acc[nt][3], 0.f);
            if (ok0) o0[nt * 4 + q] = __floats2half2_rn(v00, v01);
            if (ok1) o1[nt * 4 + q] = __floats2half2_rn(v10, v11);
            float a00 = ok0 ? v00 : 0.f, a01 = ok0 ? v01 : 0.f;
            float a10 = ok1 ? v10 : 0.f, a11 = ok1 ? v11 : 0.f;
            float s0 = a00 + a10, s1 = a01 + a11;
            float q0 = a00 * a00 + a10 * a10, q1 = a01 * a01 + a11 * a11;
#pragma unroll
            for (int m = 4; m <= 16; m <<= 1) {
                s0 += __shfl_xor_sync(0xffffffffu, s0, m);
                s1 += __shfl_xor_sync(0xffffffffu, s1, m);
                q0 += __shfl_xor_sync(0xffffffffu, q0, m);
                q1 += __shfl_xor_sync(0xffffffffu, q1, m);
            }
            if (g == 0) {
                atomicAdd(&s_st[c0],           s0);
                atomicAdd(&s_st[c0 + 1],       s1);
                atomicAdd(&s_st[128 + c0],     q0);
                atomicAdd(&s_st[128 + c0 + 1], q1);
            }
        }
        __syncthreads();
        if (tid < 256) atomicAdd(&stats[tid], s_st[tid]);
    } else {
        int blkg = s_bu;
        if (blkg >= 0) {
#pragma unroll
            for (int nt = 0; nt < 16; nt++) {
                int c0 = nt * 8 + 2 * q;
                float v00 = fmaxf(acc[nt][0], 0.f), v01 = fmaxf(acc[nt][1], 0.f);
                float v10 = fmaxf(acc[nt][2], 0.f), v11 = fmaxf(acc[nt][3], 0.f);
                float s0 = v00 + v10, s1 = v01 + v11;
                float m0 = fmaxf(v00, v10), m1 = fmaxf(v01, v11);
#pragma unroll
                for (int m = 4; m <= 16; m <<= 1) {
                    s0 += __shfl_xor_sync(0xffffffffu, s0, m);
                    s1 += __shfl_xor_sync(0xffffffffu, s1, m);
                    m0 = fmaxf(m0, __shfl_xor_sync(0xffffffffu, m0, m));
                    m1 = fmaxf(m1, __shfl_xor_sync(0xffffffffu, m1, m));
                }
                if (g == 0) {
                    atomicAdd(&s_st[c0],     s0);
                    atomicAdd(&s_st[c0 + 1], s1);
                    atomicMax(&s_sti[128 + c0],     __float_as_int(m0));
                    atomicMax(&s_sti[128 + c0 + 1], __float_as_int(m1));
                }
            }
            __syncthreads();
            if (tid < 128) {
                atomicAdd(&psum[blkg * D + tid], s_st[tid]);
                atomicMax(&pmax[blkg * D + tid], s_sti[128 + tid]);
            }
        } else {
            int rb = w * 16;
            bool whole = (base + rb + 15 < n);
            int glo = whole ? batch[base + rb] : 0;
            int ghi = whole ? batch[base + rb + 15] : -1;
            bool uniform = whole && (glo == ghi);
            if (uniform) {
#pragma unroll
                for (int nt = 0; nt < 16; nt++) {
                    int c0 = nt * 8 + 2 * q;
                    float v00 = fmaxf(acc[nt][0], 0.f), v01 = fmaxf(acc[nt][1], 0.f);
                    float v10 = fmaxf(acc[nt][2], 0.f), v11 = fmaxf(acc[nt][3], 0.f);
                    float s0 = v00 + v10, s1 = v01 + v11;
                    float m0 = fmaxf(v00, v10), m1 = fmaxf(v01, v11);
#pragma unroll
                    for (int m = 4; m <= 16; m <<= 1) {
                        s0 += __shfl_xor_sync(0xffffffffu, s0, m);
                        s1 += __shfl_xor_sync(0xffffffffu, s1, m);
                        m0 = fmaxf(m0, __shfl_xor_sync(0xffffffffu, m0, m));
                        m1 = fmaxf(m1, __shfl_xor_sync(0xffffffffu, m1, m));
                    }
                    if (g == 0) {
                        atomicAdd(&psum[glo * D + c0],     s0);
                        atomicAdd(&psum[glo * D + c0 + 1], s1);
                        atomicMax(&pmax[glo * D + c0],     __float_as_int(m0));
                        atomicMax(&pmax[glo * D + c0 + 1], __float_as_int(m1));
                    }
                }
            } else {
                int b0 = ok0 ? batch[base + row0] : 0;
                int b1i = ok1 ? batch[base + row0 + 8] : 0;
#pragma unroll
                for (int nt = 0; nt < 16; nt++) {
                    int c0 = nt * 8 + 2 * q;
                    float v00 = fmaxf(acc[nt][0], 0.f), v01 = fmaxf(acc[nt][1], 0.f);
                    float v10 = fmaxf(acc[nt][2], 0.f), v11 = fmaxf(acc[nt][3], 0.f);
                    if (ok0) {
                        atomicAdd(&psum[b0 * D + c0],     v00);
                        atomicAdd(&psum[b0 * D + c0 + 1], v01);
                        atomicMax(&pmax[b0 * D + c0],     __float_as_int(v00));
                        atomicMax(&pmax[b0 * D + c0 + 1], __float_as_int(v01));
                    }
                    if (ok1) {
                        atomicAdd(&psum[b1i * D + c0],     v10);
                        atomicAdd(&psum[b1i * D + c0 + 1], v11);
                        atomicMax(&pmax[b1i * D + c0],     __float_as_int(v10));
                        atomicMax(&pmax[b1i * D + c0 + 1], __float_as_int(v11));
                    }
                }
            }
        }
    }
}

// ================= final head (self-cleans pool buffers + cursor) =================
__device__ __forceinline__ float breduce128(float v, float* s4)
{
    int lane = threadIdx.x & 31, w = threadIdx.x >> 5;
#pragma unroll
    for (int o = 16; o; o >>= 1) v += __shfl_down_sync(0xffffffffu, v, o);
    if (lane == 0) s4[w] = v;
    __syncthreads();
    float r = s4[0] + s4[1] + s4[2] + s4[3];
    __syncthreads();
    return r;
}

__global__ __launch_bounds__(128) void final_kernel(
    float* __restrict__ psum, int* __restrict__ pmax, int* __restrict__ pcnt,
    int* __restrict__ cursor, int n,
    const float* __restrict__ Wg, const float* __restrict__ bg,
    const float* __restrict__ pb, const float* __restrict__ pm,
    const int* __restrict__ y, float* __restrict__ out)
{
    __shared__ float s_gx[2 * D];
    __shared__ float s4[4];
    int g = blockIdx.x, j = threadIdx.x;

    float cntf = fmaxf((float)pcnt[g], 1.f);
    s_gx[j]     = psum[g * D + j] / cntf;
    s_gx[D + j] = __int_as_float(pmax[g * D + j]);
    __syncthreads();

    // self-clean for the next graph replay
    psum[g * D + j] = 0.f;
    pmax[g * D + j] = 0;
    if (j == 0) pcnt[g] = 0;
    for (int i = g * 128 + j; i < n + 1; i += gridDim.x * 128) cursor[i] = 0;

    float rep = bg[j];
#pragma unroll
    for (int k = 0; k < 2 * D; k++) rep = fmaf(s_gx[k], Wg[k * D + j], rep);

    float nrm = breduce128(rep * rep, s4);
    float feat = rep / fmaxf(sqrtf(nrm), 1e-12f);

    float pbj = pb[j], pmj = pm[j];
    float nb = breduce128(pbj * pbj, s4);
    float nm = breduce128(pmj * pmj, s4);
    pbj /= fmaxf(sqrtf(nb), 1e-12f);
    pmj /= fmaxf(sqrtf(nm), 1e-12f);

    float cb = breduce128(feat * pbj, s4);
    float cm = breduce128(feat * pmj, s4);

    if (j == 0) {
        bool mal = (y[g] == 1);
        float a = mal ? cb * cb : (1.f - cb) * (1.f - cb);
        float b = mal ? (1.f - cm) * (1.f - cm) : cm * cm;
        atomicAdd(out, a + b);
    }
}

// ================= host =================
extern "C" void kernel_launch(void* const* d_in, const int* in_sizes, int n_in,
                              void* d_out, int out_size)
{
    const float* x   = (const float*)d_in[0];
    const int* ei    = (const int*)d_in[1];
    const int* batch = (const int*)d_in[2];
    const int* y     = (const int*)d_in[3];
    const float* W1  = (const float*)d_in[4];
    const float* b1  = (const float*)d_in[5];
    const float* W2  = (const float*)d_in[6];
    const float* b2  = (const float*)d_in[7];
    const float* bng = (const float*)d_in[8];
    const float* bnb = (const float*)d_in[9];
    const float* Wg  = (const float*)d_in[10];
    const float* bg  = (const float*)d_in[11];
    const float* pb  = (const float*)d_in[12];
    const float* pm  = (const float*)d_in[13];

    int n  = in_sizes[0] / D;
    int nE = in_sizes[1] / 2;
    int G  = in_sizes[3];
    const int* src = ei;
    const int* dst = ei + nE;

    __half *h16A, *h16B, *x16, *z16;
    unsigned* wt;
    float *stats;
    int *rowptr, *cursor, *partial, *csrsrc;
    void *psum, *pmax, *pcnt;
    cudaGetSymbolAddress((void**)&h16A, g_h16A);
    cudaGetSymbolAddress((void**)&h16B, g_h16B);
    cudaGetSymbolAddress((void**)&x16, g_x16);
    cudaGetSymbolAddress((void**)&z16, g_z16);
    cudaGetSymbolAddress((void**)&wt, g_wt);
    cudaGetSymbolAddress((void**)&stats, g_stats);
    cudaGetSymbolAddress((void**)&rowptr, g_rowptr);
    cudaGetSymbolAddress((void**)&cursor, g_cursor);
    cudaGetSymbolAddress((void**)&partial, g_partial);
    cudaGetSymbolAddress((void**)&csrsrc, g_csrsrc);
    cudaGetSymbolAddress(&psum, g_psum);
    cudaGetSymbolAddress(&pmax, g_pmax);
    cudaGetSymbolAddress(&pcnt, g_pcnt);

    cudaFuncSetAttribute(mlp16_kernel, cudaFuncAttributeMaxDynamicSharedMemorySize, MLP_SMEM);

    // ---- CSR build + merged hist/prep (cursor pre-zeroed by previous final_kernel) ----
    int nb = (n + SCAN_B - 1) / SCAN_B;
    int HB = (nE + 255) / 256;
    int BX = (n * 64 + 255) / 256;
    int BC = (n + 255) / 256;
    histprep_kernel<<<HB + BX + BC + 192 + 1, 256>>>(dst, cursor, nE,
                                                     x, x16, batch, (int*)pcnt,
                                                     W1, W2, stats, n, HB, BX, BC);
    scan1_kernel<<<nb, SCAN_B>>>(cursor, rowptr, partial, n);
    scan3_kernel<<<nb, SCAN_B>>>(rowptr, cursor, partial, n, nb);
    int quarter = (nE + 3) / 4;
    fill_kernel<<<(quarter + 255) / 256, 256>>>(src, dst, cursor, csrsrc, nE);

    // ---- layers (double-buffered stats, BN folded into gather) ----
    const __half* cur = x16;
    __half* nxt = h16A;
    int mlpBlocks = (n + 127) / 128;
    int gthBlocks = (n * 32 + 255) / 256;
    float inv_n = 1.f / (float)n;

    for (int l = 0; l < 3; l++) {
        float* statsPrev = stats + ((l - 1) & 1) * 256;
        float* statsCur  = stats + (l & 1) * 256;
        gather16_kernel<<<gthBlocks, 256>>>(cur, rowptr, csrsrc, z16, n,
                                            l > 0 ? 1 : 0,
                                            l > 0 ? statsPrev : stats,
                                            bng + (l > 0 ? (l - 1) : 0) * D,
                                            bnb + (l > 0 ? (l - 1) : 0) * D, inv_n);
        const unsigned* w1i = wt + (size_t)(l * 2 + 0) * WIMG;
        const unsigned* w2i = wt + (size_t)(l * 2 + 1) * WIMG;
        if (l < 2) {
            mlp16_kernel<<<mlpBlocks, 256, MLP_SMEM>>>(z16, w1i, w2i, b1 + l * D, b2 + l * D,
                nxt, statsCur, batch, (float*)psum, (int*)pmax, n, 0);
            cur = nxt;
            nxt = (l == 0) ? h16B : h16A;
        } else {
            mlp16_kernel<<<mlpBlocks, 256, MLP_SMEM>>>(z16, w1i, w2i, b1 + l * D, b2 + l * D,
                nullptr, statsCur, batch, (float*)psum, (int*)pmax, n, 2);
        }
    }

    cudaMemsetAsync(d_out, 0, sizeof(float));
    final_kernel<<<G, 128>>>((float*)psum, (int*)pmax, (int*)pcnt, cursor, n,
                             Wg, bg, pb, pm, y, (float*)d_out);
}

// round 17
// speedup vs baseline: 1.0059x; 1.0059x over previous
#include <cuda_runtime.h>
#include <cuda_fp16.h>
#include <stdint.h>
#include <math.h>

#define D 128
#define MAXN 100000
#define MAXE 1600000
#define MAXG 512

#define SZH 68            // half2 stride of A rows in smem
#define SWH 132           // half2 stride of B k2-rows in smem (and gmem image)
#define WIMG (64 * SWH)   // half2 words per weight-matrix image
#define MLP_SMEM ((128 * SZH + 64 * SWH + 256 + 256) * 4)

// ---------------- scratch ----------------
__device__ __half g_h16A[MAXN * D];
__device__ __half g_h16B[MAXN * D];
__device__ __half g_x16[MAXN * D];
__device__ __half g_z16[MAXN * D];
__device__ unsigned g_wt[3 * 2 * WIMG];   // fp16 weight images, smem-ready layout
__device__ int   g_rowptr[MAXN + 1];
__device__ int   g_cursor[MAXN + 1];      // deg histogram; zeroed at load + by final_kernel
__device__ int   g_partial[256];
__device__ int   g_csrsrc[MAXE];
__device__ int   g_rank[MAXE];            // within-bucket rank per edge
__device__ float g_stats[4 * D];          // two 256-float buffers; zeroed by prep each launch
__device__ float g_psum[MAXG * D];        // self-cleaned by final_kernel
__device__ int   g_pmax[MAXG * D];
__device__ int   g_pcnt[MAXG];

// ================= merged hist + prep =================
__global__ void histprep_kernel(const int* __restrict__ dst, int* __restrict__ deg,
                                int* __restrict__ rank, int nE,
                                const float* __restrict__ x, __half* __restrict__ x16,
                                const int* __restrict__ batch, int* __restrict__ pcnt,
                                const float* __restrict__ W1, const float* __restrict__ W2,
                                float* __restrict__ stats, int n,
                                int HB, int BX, int BC)
{
    int b = blockIdx.x;
    int tid = threadIdx.x;
    if (b < HB) {
        int e = b * 256 + tid;
        if (e < nE) rank[e] = atomicAdd(&deg[dst[e]], 1);
    } else if (b < HB + BX) {
        int i = (b - HB) * 256 + tid;
        if (i < n * 64) {
            float2 f = reinterpret_cast<const float2*>(x)[i];
            reinterpret_cast<__half2*>(x16)[i] = __floats2half2_rn(f.x, f.y);
        }
    } else if (b < HB + BX + BC) {
        int i = (b - HB - BX) * 256 + tid;
        if (i < n) atomicAdd(&pcnt[batch[i]], 1);
    } else if (b < HB + BX + BC + 192) {
        int i = (b - HB - BX - BC) * 256 + tid;
        if (i < 3 * 2 * 64 * 128) {
            int nn = i & 127;
            int k2 = (i >> 7) & 63;
            int m  = (i >> 13) & 1;
            int l  = i >> 14;
            const float* W = (m == 0 ? W1 : W2) + l * D * D;
            __half2 v = __floats2half2_rn(W[(2 * k2) * D + nn], W[(2 * k2 + 1) * D + nn]);
            int perm = (nn & 7) * 16 + (nn >> 3);
            g_wt[((l * 2 + m) * 64 + k2) * SWH + perm] = *reinterpret_cast<unsigned*>(&v);
        }
    } else {
        stats[tid] = 0.f;
        stats[256 + tid] = 0.f;
    }
}

#define SCAN_B 1024
__global__ void scan1_kernel(const int* __restrict__ deg, int* __restrict__ rowptr,
                             int* __restrict__ partial, int n)
{
    __shared__ int sh[SCAN_B];
    int i = blockIdx.x * SCAN_B + threadIdx.x;
    int v = (i < n) ? deg[i] : 0;
    sh[threadIdx.x] = v;
    __syncthreads();
    for (int o = 1; o < SCAN_B; o <<= 1) {
        int t = (threadIdx.x >= o) ? sh[threadIdx.x - o] : 0;
        __syncthreads();
        sh[threadIdx.x] += t;
        __syncthreads();
    }
    if (i < n) rowptr[i] = sh[threadIdx.x] - v;
    if (threadIdx.x == SCAN_B - 1) partial[blockIdx.x] = sh[SCAN_B - 1];
}

// adds block offsets (computed in-block from partials)
__global__ void scan3_kernel(int* __restrict__ rowptr,
                             const int* __restrict__ partial, int n, int nb)
{
    __shared__ int sp[128];
    if (threadIdx.x < nb) sp[threadIdx.x] = partial[threadIdx.x];
    __syncthreads();
    int off = 0;
    for (int k = 0; k < blockIdx.x; k++) off += sp[k];
    int i = blockIdx.x * SCAN_B + threadIdx.x;
    if (i < n) rowptr[i] += off;
    if (i == 0) {
        int total = 0;
        for (int k = 0; k < nb; k++) total += sp[k];
        rowptr[n] = total;
    }
}

// atomic-free fill: position = rowptr[dst] + precomputed rank
__global__ void fill_kernel(const int* __restrict__ src, const int* __restrict__ dst,
                            const int* __restrict__ rowptr, const int* __restrict__ rank,
                            int* __restrict__ csrsrc, int nE)
{
    int e = blockIdx.x * blockDim.x + threadIdx.x;
    if (e >= nE) return;
    csrsrc[rowptr[dst[e]] + rank[e]] = src[e];
}

// ================= gather: warp/node, half-warp per edge, inline BN fold ==========
__global__ __launch_bounds__(256) void gather16_kernel(
    const __half* __restrict__ h,
    const int* __restrict__ rowptr,
    const int* __restrict__ csrsrc,
    __half* __restrict__ z, int n, int apply_bn,
    const float* __restrict__ stats,
    const float* __restrict__ gamma, const float* __restrict__ beta, float inv_n)
{
    __shared__ float s_scale[128], s_shift[128];
    if (apply_bn) {
        if (threadIdx.x < 128) {
            int j = threadIdx.x;
            float mu = stats[j] * inv_n;
            float var = stats[D + j] * inv_n - mu * mu;
            float sc = gamma[j] * rsqrtf(var + 1e-5f);
            s_scale[j] = sc;
            s_shift[j] = beta[j] - mu * sc;
        }
        __syncthreads();
    }
    int node = (blockIdx.x * blockDim.x + threadIdx.x) >> 5;
    int lane = threadIdx.x & 31;
    int hf   = lane >> 4;
    int sl   = lane & 15;
    if (node >= n) return;
    int beg = rowptr[node], end = rowptr[node + 1];

    const uint4* h4 = reinterpret_cast<const uint4*>(h);

    float f[8];
    {
        uint4 sv = h4[(size_t)node * 16 + sl];
        const __half2* p = reinterpret_cast<const __half2*>(&sv);
        if (hf == 0) {
#pragma unroll
            for (int k = 0; k < 4; k++) {
                float2 t = __half22float2(p[k]);
                f[2 * k] = t.x; f[2 * k + 1] = t.y;
            }
        } else {
#pragma unroll
            for (int k = 0; k < 8; k++) f[k] = 0.f;
        }
    }

    const __half2 h2z = __float2half2_rn(0.f);

    for (int e0 = beg; e0 < end; e0 += 32) {
        int cnt = end - e0; if (cnt > 32) cnt = 32;
        int li = lane < cnt ? lane : cnt - 1;
        int s = csrsrc[e0 + li];

        __half2 ha[4], hb[4];
#pragma unroll
        for (int k = 0; k < 4; k++) { ha[k] = h2z; hb[k] = h2z; }

        int j = 0;
        for (; j + 4 <= cnt; j += 4) {
            int sjA = __shfl_sync(0xffffffffu, s, j + hf);
            int sjB = __shfl_sync(0xffffffffu, s, j + 2 + hf);
            uint4 va = h4[(size_t)sjA * 16 + sl];
            uint4 vb = h4[(size_t)sjB * 16 + sl];
            const __half2* pa = reinterpret_cast<const __half2*>(&va);
            const __half2* pb = reinterpret_cast<const __half2*>(&vb);
#pragma unroll
            for (int k = 0; k < 4; k++) {
                ha[k] = __hadd2(ha[k], pa[k]);
                hb[k] = __hadd2(hb[k], pb[k]);
            }
        }
        for (; j < cnt; j += 2) {
            int idx = j + hf;
            bool ok = idx < cnt;
            int sj = __shfl_sync(0xffffffffu, s, ok ? idx : 0);
            if (ok) {
                uint4 va = h4[(size_t)sj * 16 + sl];
                const __half2* pa = reinterpret_cast<const __half2*>(&va);
#pragma unroll
                for (int k = 0; k < 4; k++) ha[k] = __hadd2(ha[k], pa[k]);
            }
        }
        // flush chunk (each half2 acc held <= 8 fp16 adds)
#pragma unroll
        for (int k = 0; k < 4; k++) {
            float2 t0 = __half22float2(ha[k]);
            float2 t1 = __half22float2(hb[k]);
            f[2 * k]     += t0.x + t1.x;
            f[2 * k + 1] += t0.y + t1.y;
        }
    }

#pragma unroll
    for (int k = 0; k < 8; k++) f[k] += __shfl_xor_sync(0xffffffffu, f[k], 16);

    if (hf == 0) {
        if (apply_bn) {
            float m = 1.f + (float)(end - beg);
            int jb = sl * 8;
#pragma unroll
            for (int k = 0; k < 8; k++)
                f[k] = fmaf(f[k], s_scale[jb + k], m * s_shift[jb + k]);
        }
        uint4 out;
        __half2* o = reinterpret_cast<__half2*>(&out);
#pragma unroll
        for (int k = 0; k < 4; k++) o[k] = __floats2half2_rn(f[2 * k], f[2 * k + 1]);
        reinterpret_cast<uint4*>(z)[(size_t)node * 16 + sl] = out;
    }
}

// ================= fp16 tensor-core fused MLP (m16n8k16) =================
__device__ __forceinline__ void mma_f16(float* c, unsigned a0, unsigned a1,
                                        unsigned a2, unsigned a3,
                                        unsigned b0, unsigned b1)
{
    asm volatile("mma.sync.aligned.m16n8k16.row.col.f32.f16.f16.f32 "
                 "{%0,%1,%2,%3}, {%4,%5,%6,%7}, {%8,%9}, {%0,%1,%2,%3};"
                 : "+f"(c[0]), "+f"(c[1]), "+f"(c[2]), "+f"(c[3])
                 : "r"(a0), "r"(a1), "r"(a2), "r"(a3), "r"(b0), "r"(b1));
}

// mode 0: write h16 out + fused BN stats.  mode 2: fused mean/max pooling.
__global__ __launch_bounds__(256, 1) void mlp16_kernel(
    const __half* __restrict__ z,
    const unsigned* __restrict__ wimg1, const unsigned* __restrict__ wimg2,
    const float* __restrict__ b1, const float* __restrict__ b2,
    __half* __restrict__ hout, float* __restrict__ stats,
    const int* __restrict__ batch, float* __restrict__ psum, int* __restrict__ pmax,
    int n, int mode)
{
    extern __shared__ unsigned smu[];
    unsigned* s_z = smu;                               // [128][SZH] half2
    unsigned* s_w = smu + 128 * SZH;                   // [64][SWH] half2
    float* s_b1 = reinterpret_cast<float*>(smu + 128 * SZH + 64 * SWH);
    float* s_b2 = s_b1 + 128;
    float* s_st = s_b2 + 128;                          // [256] sum/sumsq (mode0) or sum/max (mode2)
    int*   s_sti = reinterpret_cast<int*>(s_st);
    __shared__ int s_bu;

    int tid  = threadIdx.x;
    int w    = tid >> 5;
    int lane = tid & 31;
    int g    = lane >> 2;
    int q    = lane & 3;
    int base = blockIdx.x * 128;
    int cnt  = n - base; if (cnt > 128) cnt = 128;

    if (tid < 128)      s_b1[tid] = b1[tid];
    else                s_b2[tid - 128] = b2[tid - 128];
    if (tid < 256)      s_st[tid] = 0.f;
    if (tid == 0)
        s_bu = (mode == 2 && cnt == 128 && batch[base] == batch[base + 127]) ? batch[base] : -1;

    // load Z tile (fp16, strided rows)
    const uint4* z4 = reinterpret_cast<const uint4*>(z);
#pragma unroll
    for (int it = 0; it < 8; it++) {
        int i = it * 256 + tid;
        int r = i >> 4, c8 = i & 15;
        uint4 v = (r < cnt) ? z4[(size_t)(base + r) * 16 + c8] : make_uint4(0u, 0u, 0u, 0u);
        *reinterpret_cast<uint4*>(s_z + r * SZH + c8 * 4) = v;
    }
    // load W1 image
    const uint4* w14 = reinterpret_cast<const uint4*>(wimg1);
#pragma unroll
    for (int it = 0; it < 9; it++) {
        int i = it * 256 + tid;
        if (i < WIMG / 4) reinterpret_cast<uint4*>(s_w)[i] = w14[i];
    }
    __syncthreads();

    int row0 = w * 16 + g;

    // ---- GEMM1: T = relu(Z @ W1 + b1) ----
    float acc[16][4];
#pragma unroll
    for (int nt = 0; nt < 16; nt++) {
        float bv0 = s_b1[nt * 8 + 2 * q], bv1 = s_b1[nt * 8 + 2 * q + 1];
        acc[nt][0] = bv0; acc[nt][1] = bv1; acc[nt][2] = bv0; acc[nt][3] = bv1;
    }
#pragma unroll
    for (int k8 = 0; k8 < 8; k8++) {
        int kq = k8 * 8 + q;
        unsigned a0 = s_z[row0 * SZH + kq];
        unsigned a1 = s_z[(row0 + 8) * SZH + kq];
        unsigned a2 = s_z[row0 * SZH + kq + 4];
        unsigned a3 = s_z[(row0 + 8) * SZH + kq + 4];
        unsigned B0[16], B1[16];
        const unsigned* r0p = s_w + kq * SWH + g * 16;
        const unsigned* r1p = s_w + (kq + 4) * SWH + g * 16;
        *reinterpret_cast<uint4*>(&B0[0])  = *reinterpret_cast<const uint4*>(r0p + 0);
        *reinterpret_cast<uint4*>(&B0[4])  = *reinterpret_cast<const uint4*>(r0p + 4);
        *reinterpret_cast<uint4*>(&B0[8])  = *reinterpret_cast<const uint4*>(r0p + 8);
        *reinterpret_cast<uint4*>(&B0[12]) = *reinterpret_cast<const uint4*>(r0p + 12);
        *reinterpret_cast<uint4*>(&B1[0])  = *reinterpret_cast<const uint4*>(r1p + 0);
        *reinterpret_cast<uint4*>(&B1[4])  = *reinterpret_cast<const uint4*>(r1p + 4);
        *reinterpret_cast<uint4*>(&B1[8])  = *reinterpret_cast<const uint4*>(r1p + 8);
        *reinterpret_cast<uint4*>(&B1[12]) = *reinterpret_cast<const uint4*>(r1p + 12);
#pragma unroll
        for (int nt = 0; nt < 16; nt++)
            mma_f16(acc[nt], a0, a1, a2, a3, B0[nt], B1[nt]);
    }
    __syncthreads();

    // store relu(T) as fp16 into freed s_z; load W2 image
#pragma unroll
    for (int nt = 0; nt < 16; nt++) {
        int hI = nt * 4 + q;
        __half2 v0 = __floats2half2_rn(fmaxf(acc[nt][0], 0.f), fmaxf(acc[nt][1], 0.f));
        __half2 v1 = __floats2half2_rn(fmaxf(acc[nt][2], 0.f), fmaxf(acc[nt][3], 0.f));
        s_z[row0 * SZH + hI]       = *reinterpret_cast<unsigned*>(&v0);
        s_z[(row0 + 8) * SZH + hI] = *reinterpret_cast<unsigned*>(&v1);
    }
    const uint4* w24 = reinterpret_cast<const uint4*>(wimg2);
#pragma unroll
    for (int it = 0; it < 9; it++) {
        int i = it * 256 + tid;
        if (i < WIMG / 4) reinterpret_cast<uint4*>(s_w)[i] = w24[i];
    }
    __syncthreads();

    // ---- GEMM2: H = relu(T @ W2 + b2) ----
#pragma unroll
    for (int nt = 0; nt < 16; nt++) {
        float bv0 = s_b2[nt * 8 + 2 * q], bv1 = s_b2[nt * 8 + 2 * q + 1];
        acc[nt][0] = bv0; acc[nt][1] = bv1; acc[nt][2] = bv0; acc[nt][3] = bv1;
    }
#pragma unroll
    for (int k8 = 0; k8 < 8; k8++) {
        int kq = k8 * 8 + q;
        unsigned a0 = s_z[row0 * SZH + kq];
        unsigned a1 = s_z[(row0 + 8) * SZH + kq];
        unsigned a2 = s_z[row0 * SZH + kq + 4];
        unsigned a3 = s_z[(row0 + 8) * SZH + kq + 4];
        unsigned B0[16], B1[16];
        const unsigned* r0p = s_w + kq * SWH + g * 16;
        const unsigned* r1p = s_w + (kq + 4) * SWH + g * 16;
        *reinterpret_cast<uint4*>(&B0[0])  = *reinterpret_cast<const uint4*>(r0p + 0);
        *reinterpret_cast<uint4*>(&B0[4])  = *reinterpret_cast<const uint4*>(r0p + 4);
        *reinterpret_cast<uint4*>(&B0[8])  = *reinterpret_cast<const uint4*>(r0p + 8);
        *reinterpret_cast<uint4*>(&B0[12]) = *reinterpret_cast<const uint4*>(r0p + 12);
        *reinterpret_cast<uint4*>(&B1[0])  = *reinterpret_cast<const uint4*>(r1p + 0);
        *reinterpret_cast<uint4*>(&B1[4])  = *reinterpret_cast<const uint4*>(r1p + 4);
        *reinterpret_cast<uint4*>(&B1[8])  = *reinterpret_cast<const uint4*>(r1p + 8);
        *reinterpret_cast<uint4*>(&B1[12]) = *reinterpret_cast<const uint4*>(r1p + 12);
#pragma unroll
        for (int nt = 0; nt < 16; nt++)
            mma_f16(acc[nt], a0, a1, a2, a3, B0[nt], B1[nt]);
    }

    bool ok0 = (row0 < cnt), ok1 = (row0 + 8 < cnt);

    if (mode != 2) {
        __half2* o0 = reinterpret_cast<__half2*>(hout + (size_t)(base + row0) * 128);
        __half2* o1 = reinterpret_cast<__half2*>(hout + (size_t)(base + row0 + 8) * 128);
#pragma unroll
        for (int nt = 0; nt < 16; nt++) {
            int c0 = nt * 8 + 2 * q;
            float v00 = fmaxf(acc[nt][0], 0.f), v01 = fmaxf(acc[nt][1], 0.f);
            float v10 = fmaxf(acc[nt][2], 0.f), v11 = fmaxf(acc[nt][3], 0.f);
            if (ok0) o0[nt * 4 + q] = __floats2half2_rn(v00, v01);
            if (ok1) o1[nt * 4 + q] = __floats2half2_rn(v10, v11);
            float a00 = ok0 ? v00 : 0.f, a01 = ok0 ? v01 : 0.f;
            float a10 = ok1 ? v10 : 0.f, a11 = ok1 ? v11 : 0.f;
            float s0 = a00 + a10, s1 = a01 + a11;
            float q0 = a00 * a00 + a10 * a10, q1 = a01 * a01 + a11 * a11;
#pragma unroll
            for (int m = 4; m <= 16; m <<= 1) {
                s0 += __shfl_xor_sync(0xffffffffu, s0, m);
                s1 += __shfl_xor_sync(0xffffffffu, s1, m);
                q0 += __shfl_xor_sync(0xffffffffu, q0, m);
                q1 += __shfl_xor_sync(0xffffffffu, q1, m);
            }
            if (g == 0) {
                atomicAdd(&s_st[c0],           s0);
                atomicAdd(&s_st[c0 + 1],       s1);
                atomicAdd(&s_st[128 + c0],     q0);
                atomicAdd(&s_st[128 + c0 + 1], q1);
            }
        }
        __syncthreads();
        if (tid < 256) atomicAdd(&stats[tid], s_st[tid]);
    } else {
        int blkg = s_bu;
        if (blkg >= 0) {
#pragma unroll
            for (int nt = 0; nt < 16; nt++) {
                int c0 = nt * 8 + 2 * q;
                float v00 = fmaxf(acc[nt][0], 0.f), v01 = fmaxf(acc[nt][1], 0.f);
                float v10 = fmaxf(acc[nt][2], 0.f), v11 = fmaxf(acc[nt][3], 0.f);
                float s0 = v00 + v10, s1 = v01 + v11;
                float m0 = fmaxf(v00, v10), m1 = fmaxf(v01, v11);
#pragma unroll
                for (int m = 4; m <= 16; m <<= 1) {
                    s0 += __shfl_xor_sync(0xffffffffu, s0, m);
                    s1 += __shfl_xor_sync(0xffffffffu, s1, m);
                    m0 = fmaxf(m0, __shfl_xor_sync(0xffffffffu, m0, m));
                    m1 = fmaxf(m1, __shfl_xor_sync(0xffffffffu, m1, m));
                }
                if (g == 0) {
                    atomicAdd(&s_st[c0],     s0);
                    atomicAdd(&s_st[c0 + 1], s1);
                    atomicMax(&s_sti[128 + c0],     __float_as_int(m0));
                    atomicMax(&s_sti[128 + c0 + 1], __float_as_int(m1));
                }
            }
            __syncthreads();
            if (tid < 128) {
                atomicAdd(&psum[blkg * D + tid], s_st[tid]);
                atomicMax(&pmax[blkg * D + tid], s_sti[128 + tid]);
            }
        } else {
            int rb = w * 16;
            bool whole = (base + rb + 15 < n);
            int glo = whole ? batch[base + rb] : 0;
            int ghi = whole ? batch[base + rb + 15] : -1;
            bool uniform = whole && (glo == ghi);
            if (uniform) {
#pragma unroll
                for (int nt = 0; nt < 16; nt++) {
                    int c0 = nt * 8 + 2 * q;
                    float v00 = fmaxf(acc[nt][0], 0.f), v01 = fmaxf(acc[nt][1], 0.f);
                    float v10 = fmaxf(acc[nt][2], 0.f), v11 = fmaxf(acc[nt][3], 0.f);
                    float s0 = v00 + v10, s1 = v01 + v11;
                    float m0 = fmaxf(v00, v10), m1 = fmaxf(v01, v11);
#pragma unroll
                    for (int m = 4; m <= 16; m <<= 1) {
                        s0 += __shfl_xor_sync(0xffffffffu, s0, m);
                        s1 += __shfl_xor_sync(0xffffffffu, s1, m);
                        m0 = fmaxf(m0, __shfl_xor_sync(0xffffffffu, m0, m));
                        m1 = fmaxf(m1, __shfl_xor_sync(0xffffffffu, m1, m));
                    }
                    if (g == 0) {
                        atomicAdd(&psum[glo * D + c0],     s0);
                        atomicAdd(&psum[glo * D + c0 + 1], s1);
                        atomicMax(&pmax[glo * D + c0],     __float_as_int(m0));
                        atomicMax(&pmax[glo * D + c0 + 1], __float_as_int(m1));
                    }
                }
            } else {
                int b0 = ok0 ? batch[base + row0] : 0;
                int b1i = ok1 ? batch[base + row0 + 8] : 0;
#pragma unroll
                for (int nt = 0; nt < 16; nt++) {
                    int c0 = nt * 8 + 2 * q;
                    float v00 = fmaxf(acc[nt][0], 0.f), v01 = fmaxf(acc[nt][1], 0.f);
                    float v10 = fmaxf(acc[nt][2], 0.f), v11 = fmaxf(acc[nt][3], 0.f);
                    if (ok0) {
                        atomicAdd(&psum[b0 * D + c0],     v00);
                        atomicAdd(&psum[b0 * D + c0 + 1], v01);
                        atomicMax(&pmax[b0 * D + c0],     __float_as_int(v00));
                        atomicMax(&pmax[b0 * D + c0 + 1], __float_as_int(v01));
                    }
                    if (ok1) {
                        atomicAdd(&psum[b1i * D + c0],     v10);
                        atomicAdd(&psum[b1i * D + c0 + 1], v11);
                        atomicMax(&pmax[b1i * D + c0],     __float_as_int(v10));
                        atomicMax(&pmax[b1i * D + c0 + 1], __float_as_int(v11));
                    }
                }
            }
        }
    }
}

// ================= final head (self-cleans pool buffers + deg histogram) ==========
__device__ __forceinline__ float breduce128(float v, float* s4)
{
    int lane = threadIdx.x & 31, w = threadIdx.x >> 5;
#pragma unroll
    for (int o = 16; o; o >>= 1) v += __shfl_down_sync(0xffffffffu, v, o);
    if (lane == 0) s4[w] = v;
    __syncthreads();
    float r = s4[0] + s4[1] + s4[2] + s4[3];
    __syncthreads();
    return r;
}

__global__ __launch_bounds__(128) void final_kernel(
    float* __restrict__ psum, int* __restrict__ pmax, int* __restrict__ pcnt,
    int* __restrict__ deg, int n,
    const float* __restrict__ Wg, const float* __restrict__ bg,
    const float* __restrict__ pb, const float* __restrict__ pm,
    const int* __restrict__ y, float* __restrict__ out)
{
    __shared__ float s_gx[2 * D];
    __shared__ float s4[4];
    int g = blockIdx.x, j = threadIdx.x;

    float cntf = fmaxf((float)pcnt[g], 1.f);
    s_gx[j]     = psum[g * D + j] / cntf;
    s_gx[D + j] = __int_as_float(pmax[g * D + j]);
    __syncthreads();

    // self-clean for the next graph replay
    psum[g * D + j] = 0.f;
    pmax[g * D + j] = 0;
    if (j == 0) pcnt[g] = 0;
    for (int i = g * 128 + j; i < n + 1; i += gridDim.x * 128) deg[i] = 0;

    float rep = bg[j];
#pragma unroll
    for (int k = 0; k < 2 * D; k++) rep = fmaf(s_gx[k], Wg[k * D + j], rep);

    float nrm = breduce128(rep * rep, s4);
    float feat = rep / fmaxf(sqrtf(nrm), 1e-12f);

    float pbj = pb[j], pmj = pm[j];
    float nb = breduce128(pbj * pbj, s4);
    float nm = breduce128(pmj * pmj, s4);
    pbj /= fmaxf(sqrtf(nb), 1e-12f);
    pmj /= fmaxf(sqrtf(nm), 1e-12f);

    float cb = breduce128(feat * pbj, s4);
    float cm = breduce128(feat * pmj, s4);

    if (j == 0) {
        bool mal = (y[g] == 1);
        float a = mal ? cb * cb : (1.f - cb) * (1.f - cb);
        float b = mal ? (1.f - cm) * (1.f - cm) : cm * cm;
        atomicAdd(out, a + b);
    }
}

// ================= host =================
extern "C" void kernel_launch(void* const* d_in, const int* in_sizes, int n_in,
                              void* d_out, int out_size)
{
    const float* x   = (const float*)d_in[0];
    const int* ei    = (const int*)d_in[1];
    const int* batch = (const int*)d_in[2];
    const int* y     = (const int*)d_in[3];
    const float* W1  = (const float*)d_in[4];
    const float* b1  = (const float*)d_in[5];
    const float* W2  = (const float*)d_in[6];
    const float* b2  = (const float*)d_in[7];
    const float* bng = (const float*)d_in[8];
    const float* bnb = (const float*)d_in[9];
    const float* Wg  = (const float*)d_in[10];
    const float* bg  = (const float*)d_in[11];
    const float* pb  = (const float*)d_in[12];
    const float* pm  = (const float*)d_in[13];

    int n  = in_sizes[0] / D;
    int nE = in_sizes[1] / 2;
    int G  = in_sizes[3];
    const int* src = ei;
    const int* dst = ei + nE;

    __half *h16A, *h16B, *x16, *z16;
    unsigned* wt;
    float *stats;
    int *rowptr, *cursor, *partial, *csrsrc, *rank;
    void *psum, *pmax, *pcnt;
    cudaGetSymbolAddress((void**)&h16A, g_h16A);
    cudaGetSymbolAddress((void**)&h16B, g_h16B);
    cudaGetSymbolAddress((void**)&x16, g_x16);
    cudaGetSymbolAddress((void**)&z16, g_z16);
    cudaGetSymbolAddress((void**)&wt, g_wt);
    cudaGetSymbolAddress((void**)&stats, g_stats);
    cudaGetSymbolAddress((void**)&rowptr, g_rowptr);
    cudaGetSymbolAddress((void**)&cursor, g_cursor);
    cudaGetSymbolAddress((void**)&partial, g_partial);
    cudaGetSymbolAddress((void**)&csrsrc, g_csrsrc);
    cudaGetSymbolAddress((void**)&rank, g_rank);
    cudaGetSymbolAddress(&psum, g_psum);
    cudaGetSymbolAddress(&pmax, g_pmax);
    cudaGetSymbolAddress(&pcnt, g_pcnt);

    cudaFuncSetAttribute(mlp16_kernel, cudaFuncAttributeMaxDynamicSharedMemorySize, MLP_SMEM);

    // ---- CSR build + merged hist/prep (deg pre-zeroed by previous final_kernel) ----
    int nb = (n + SCAN_B - 1) / SCAN_B;
    int HB = (nE + 255) / 256;
    int BX = (n * 64 + 255) / 256;
    int BC = (n + 255) / 256;
    histprep_kernel<<<HB + BX + BC + 192 + 1, 256>>>(dst, cursor, rank, nE,
                                                     x, x16, batch, (int*)pcnt,
                                                     W1, W2, stats, n, HB, BX, BC);
    scan1_kernel<<<nb, SCAN_B>>>(cursor, rowptr, partial, n);
    scan3_kernel<<<nb, SCAN_B>>>(rowptr, partial, n, nb);
    fill_kernel<<<(nE + 255) / 256, 256>>>(src, dst, rowptr, rank, csrsrc, nE);

    // ---- layers (double-buffered stats, BN folded into gather) ----
    const __half* cur = x16;
    __half* nxt = h16A;
    int mlpBlocks = (n + 127) / 128;
    int gthBlocks = (n * 32 + 255) / 256;
    float inv_n = 1.f / (float)n;

    for (int l = 0; l < 3; l++) {
        float* statsPrev = stats + ((l - 1) & 1) * 256;
        float* statsCur  = stats + (l & 1) * 256;
        gather16_kernel<<<gthBlocks, 256>>>(cur, rowptr, csrsrc, z16, n,
                                            l > 0 ? 1 : 0,
                                            l > 0 ? statsPrev : stats,
                                            bng + (l > 0 ? (l - 1) : 0) * D,
                                            bnb + (l > 0 ? (l - 1) : 0) * D, inv_n);
        const unsigned* w1i = wt + (size_t)(l * 2 + 0) * WIMG;
        const unsigned* w2i = wt + (size_t)(l * 2 + 1) * WIMG;
        if (l < 2) {
            mlp16_kernel<<<mlpBlocks, 256, MLP_SMEM>>>(z16, w1i, w2i, b1 + l * D, b2 + l * D,
                nxt, statsCur, batch, (float*)psum, (int*)pmax, n, 0);
            cur = nxt;
            nxt = (l == 0) ? h16B : h16A;
        } else {
            mlp16_kernel<<<mlpBlocks, 256, MLP_SMEM>>>(z16, w1i, w2i, b1 + l * D, b2 + l * D,
                nullptr, statsCur, batch, (float*)psum, (int*)pmax, n, 2);
        }
    }

    cudaMemsetAsync(d_out, 0, sizeof(float));
    final_kernel<<<G, 128>>>((float*)psum, (int*)pmax, (int*)pcnt, cursor, n,
                             Wg, bg, pb, pm, y, (float*)d_out);
}